// round 3
// baseline (speedup 1.0000x reference)
#include <cuda_runtime.h>
#include <math.h>

#define NN 4000
#define NE 60000
#define MDIM 16
#define CDIM 64
#define HDIM 64
#define NHEADS 8
#define ADIM 8
#define VCDIM 8
#define CEDIM 32

// ---- scratch (__device__ globals: no allocation allowed) ----
__device__ float g_ex[NE * NHEADS];          // exp(logits) per edge
__device__ float g_segsum[NN * NHEADS];      // softmax denominators per (node, head)
__device__ float g_WsT[2][HDIM * CDIM];      // WsT[blk][h*64+c] = Ws[c*64+h]
__device__ float g_WtT[2][HDIM * CDIM];
__device__ float g_WeT[2][HDIM * CEDIM];     // WeT[blk][h*32+ce] = We[ce*64+h]
__device__ float g_PT[2][NHEADS * HDIM];     // PT[blk][h*64+c] = sum_vc Wv[c,h*8+vc]*Wo[h*8+vc]

__device__ __forceinline__ float silu_f(float v) { return v / (1.0f + __expf(-v)); }

// ---------------------------------------------------------------------------
// K0: zero accumulators + build derived small matrices
// ---------------------------------------------------------------------------
__global__ void setup_kernel(
    const float* __restrict__ fs_We, const float* __restrict__ fs_Ws, const float* __restrict__ fs_Wt,
    const float* __restrict__ fs_Wv, const float* __restrict__ fs_Wo,
    const float* __restrict__ dn_We, const float* __restrict__ dn_Ws, const float* __restrict__ dn_Wt,
    const float* __restrict__ dn_Wv, const float* __restrict__ dn_Wo,
    float* __restrict__ out)
{
    int tid = blockIdx.x * blockDim.x + threadIdx.x;
    int nt  = gridDim.x * blockDim.x;

    for (int i = tid; i < NN * 3; i += nt) out[i] = 0.0f;
    for (int i = tid; i < NN * NHEADS; i += nt) g_segsum[i] = 0.0f;

    // WsT / WtT
    for (int i = tid; i < 2 * CDIM * HDIM; i += nt) {
        int blk = i >> 12; int r = i & 4095;
        int h = r >> 6; int c = r & 63;
        const float* Ws = blk ? dn_Ws : fs_Ws;
        const float* Wt = blk ? dn_Wt : fs_Wt;
        g_WsT[blk][h * CDIM + c] = Ws[c * HDIM + h];
        g_WtT[blk][h * CDIM + c] = Wt[c * HDIM + h];
    }
    // WeT
    for (int i = tid; i < 2 * HDIM * CEDIM; i += nt) {
        int blk = i >> 11; int r = i & 2047;
        int h = r >> 5; int ce = r & 31;
        const float* We = blk ? dn_We : fs_We;
        g_WeT[blk][h * CEDIM + ce] = We[ce * HDIM + h];
    }
    // PT
    for (int i = tid; i < 2 * NHEADS * HDIM; i += nt) {
        int blk = i >> 9; int r = i & 511;
        int h = r >> 6; int c = r & 63;
        const float* Wv = blk ? dn_Wv : fs_Wv;
        const float* Wo = blk ? dn_Wo : fs_Wo;
        float acc = 0.0f;
#pragma unroll
        for (int vc = 0; vc < VCDIM; vc++)
            acc += Wv[c * (NHEADS * VCDIM) + h * VCDIM + vc] * Wo[h * VCDIM + vc];
        g_PT[blk][h * HDIM + c] = acc;
    }
}

// ---------------------------------------------------------------------------
// K1: per-edge logits + exp + segment sum.  One warp per edge.
// ---------------------------------------------------------------------------
__global__ void __launch_bounds__(256)
pass1_kernel(
    const float* __restrict__ x, const int* __restrict__ zn,
    const float* __restrict__ dist, const int* __restrict__ eidx,
    const int* __restrict__ mask, const float* __restrict__ wig,
    const float* __restrict__ fs_emb_s, const float* __restrict__ fs_emb_t,
    const float* __restrict__ fs_wd, const float* __restrict__ fs_We,
    const float* __restrict__ fs_Ws, const float* __restrict__ fs_Wt,
    const float* __restrict__ fs_Wa, const float* __restrict__ fs_va,
    const float* __restrict__ dn_emb_s, const float* __restrict__ dn_emb_t,
    const float* __restrict__ dn_wd, const float* __restrict__ dn_We,
    const float* __restrict__ dn_Ws, const float* __restrict__ dn_Wt,
    const float* __restrict__ dn_Wa, const float* __restrict__ dn_va)
{
    __shared__ float sh_d0[8][16];
    __shared__ float sh_us[8][64];
    __shared__ float sh_ut[8][64];
    __shared__ float sh_e [8][32];
    __shared__ float sh_f0[8][64];
    __shared__ float sh_av[8][64];

    const int w    = threadIdx.x >> 5;
    const int lane = threadIdx.x & 31;
    const int e    = blockIdx.x * 8 + w;
    if (e >= NE) return;

    const int s   = eidx[e];
    const int d   = eidx[NE + e];
    const int blk = mask[d] ? 1 : 0;

    // D row 0
    if (lane < 16) sh_d0[w][lane] = wig[(long)e * 256 + lane];
    __syncwarp();

    // u_s = D0 @ x[src], u_t = D0 @ x[dst]   (lane owns channels 2*lane, 2*lane+1)
    {
        const float2* xs2 = (const float2*)(x + (long)s * 1024);
        const float2* xt2 = (const float2*)(x + (long)d * 1024);
        float2 us = make_float2(0.f, 0.f), ut = make_float2(0.f, 0.f);
#pragma unroll
        for (int n = 0; n < MDIM; n++) {
            float dn0 = sh_d0[w][n];
            float2 a = xs2[n * 32 + lane];
            float2 b = xt2[n * 32 + lane];
            us.x += dn0 * a.x; us.y += dn0 * a.y;
            ut.x += dn0 * b.x; ut.y += dn0 * b.y;
        }
        ((float2*)sh_us[w])[lane] = us;
        ((float2*)sh_ut[w])[lane] = ut;
    }

    // edge scalar embedding e = silu(dist*w_d + emb_s[zs] + emb_t[zd])   (CE=32, one per lane)
    {
        const float* emb_s = blk ? dn_emb_s : fs_emb_s;
        const float* emb_t = blk ? dn_emb_t : fs_emb_t;
        const float* wd    = blk ? dn_wd    : fs_wd;
        int zs = zn[s], zd = zn[d];
        float dd = dist[e];
        float ev = dd * wd[lane] + emb_s[zs * CEDIM + lane] + emb_t[zd * CEDIM + lane];
        sh_e[w][lane] = silu_f(ev);
    }
    __syncwarp();

    // f0[h] = u_s@Ws + u_t@Wt + e@We     (lane owns h = 2*lane, 2*lane+1)
    {
        const float* Ws = blk ? dn_Ws : fs_Ws;
        const float* Wt = blk ? dn_Wt : fs_Wt;
        const float* We = blk ? dn_We : fs_We;
        float2 f0 = make_float2(0.f, 0.f);
#pragma unroll 8
        for (int c = 0; c < CDIM; c++) {
            float ucs = sh_us[w][c], uct = sh_ut[w][c];
            float2 ws = *(const float2*)(Ws + c * HDIM + 2 * lane);
            float2 wt = *(const float2*)(Wt + c * HDIM + 2 * lane);
            f0.x += ucs * ws.x + uct * wt.x;
            f0.y += ucs * ws.y + uct * wt.y;
        }
#pragma unroll 8
        for (int ce = 0; ce < CEDIM; ce++) {
            float ev = sh_e[w][ce];
            float2 we = *(const float2*)(We + ce * HDIM + 2 * lane);
            f0.x += ev * we.x; f0.y += ev * we.y;
        }
        ((float2*)sh_f0[w])[lane] = f0;
    }
    __syncwarp();

    // a = leaky_relu(f0 @ Wa, 0.2); av = a * va ; logits = head-sums of av
    {
        const float* Wa = blk ? dn_Wa : fs_Wa;
        const float* va = blk ? dn_va : fs_va;
        float2 acc = make_float2(0.f, 0.f);
#pragma unroll 8
        for (int h = 0; h < HDIM; h++) {
            float fh = sh_f0[w][h];
            float2 wa = *(const float2*)(Wa + h * (NHEADS * ADIM) + 2 * lane);
            acc.x += fh * wa.x; acc.y += fh * wa.y;
        }
        acc.x = acc.x > 0.f ? acc.x : 0.2f * acc.x;
        acc.y = acc.y > 0.f ? acc.y : 0.2f * acc.y;
        float2 vv = *(const float2*)(va + 2 * lane);
        float2 av = make_float2(acc.x * vv.x, acc.y * vv.y);
        ((float2*)sh_av[w])[lane] = av;
    }
    __syncwarp();

    if (lane < NHEADS) {
        float lg = 0.f;
#pragma unroll
        for (int a = 0; a < ADIM; a++) lg += sh_av[w][lane * ADIM + a];
        float ex = expf(lg);
        g_ex[(long)e * NHEADS + lane] = ex;
        atomicAdd(&g_segsum[d * NHEADS + lane], ex);
    }
}

// ---------------------------------------------------------------------------
// K2: per-edge output contribution.  One warp per edge.
// c[e,j] = x_s[j,:]·(Ws q) + x_t[j,:]·(Wt q) + D0[j]·(e·(We q)),  j=1..3
// ---------------------------------------------------------------------------
__global__ void __launch_bounds__(256)
pass2_kernel(
    const float* __restrict__ x, const int* __restrict__ zn,
    const float* __restrict__ dist, const int* __restrict__ eidx,
    const int* __restrict__ mask, const float* __restrict__ wig,
    const float* __restrict__ fs_emb_s, const float* __restrict__ fs_emb_t,
    const float* __restrict__ fs_wd,
    const float* __restrict__ dn_emb_s, const float* __restrict__ dn_emb_t,
    const float* __restrict__ dn_wd,
    float* __restrict__ out)
{
    __shared__ float sh_alpha[8][NHEADS];
    __shared__ float sh_q[8][HDIM];

    const int w    = threadIdx.x >> 5;
    const int lane = threadIdx.x & 31;
    const int e    = blockIdx.x * 8 + w;
    if (e >= NE) return;

    const int s   = eidx[e];
    const int d   = eidx[NE + e];
    const int blk = mask[d] ? 1 : 0;

    if (lane < NHEADS) {
        float ex = g_ex[(long)e * NHEADS + lane];
        sh_alpha[w][lane] = ex / (g_segsum[d * NHEADS + lane] + 1e-9f);
    }
    __syncwarp();

    // q = P @ alpha  (lane owns c = 2*lane, 2*lane+1)
    {
        float2 q = make_float2(0.f, 0.f);
#pragma unroll
        for (int h = 0; h < NHEADS; h++) {
            float al = sh_alpha[w][h];
            float2 p = *(const float2*)(&g_PT[blk][h * HDIM + 2 * lane]);
            q.x += al * p.x; q.y += al * p.y;
        }
        ((float2*)sh_q[w])[lane] = q;
    }
    __syncwarp();

    // rs = Ws@q, rt = Wt@q (per-lane channel pair); wq = (We@q)[lane] for t-term
    float2 rs = make_float2(0.f, 0.f), rt = make_float2(0.f, 0.f);
    float wq = 0.f;
#pragma unroll 8
    for (int h = 0; h < HDIM; h++) {
        float qh = sh_q[w][h];
        float2 a = *(const float2*)(&g_WsT[blk][h * CDIM + 2 * lane]);
        float2 b = *(const float2*)(&g_WtT[blk][h * CDIM + 2 * lane]);
        rs.x += qh * a.x; rs.y += qh * a.y;
        rt.x += qh * b.x; rt.y += qh * b.y;
        wq += qh * g_WeT[blk][h * CEDIM + lane];
    }

    // t-term partial: e[lane] * (We q)[lane]   (CE == 32 == warp size)
    float tpart;
    {
        const float* emb_s = blk ? dn_emb_s : fs_emb_s;
        const float* emb_t = blk ? dn_emb_t : fs_emb_t;
        const float* wd    = blk ? dn_wd    : fs_wd;
        int zs = zn[s], zd = zn[d];
        float dd = dist[e];
        float ev = silu_f(dd * wd[lane] + emb_s[zs * CEDIM + lane] + emb_t[zd * CEDIM + lane]);
        tpart = ev * wq;
    }

    // s_j partials for j = 1..3
    const float2* xs2 = (const float2*)(x + (long)s * 1024);
    const float2* xt2 = (const float2*)(x + (long)d * 1024);
    float p1, p2, p3;
    {
        float2 a = xs2[1 * 32 + lane], b = xt2[1 * 32 + lane];
        p1 = a.x * rs.x + a.y * rs.y + b.x * rt.x + b.y * rt.y;
        a = xs2[2 * 32 + lane]; b = xt2[2 * 32 + lane];
        p2 = a.x * rs.x + a.y * rs.y + b.x * rt.x + b.y * rt.y;
        a = xs2[3 * 32 + lane]; b = xt2[3 * 32 + lane];
        p3 = a.x * rs.x + a.y * rs.y + b.x * rt.x + b.y * rt.y;
    }

    // warp reduce 4 scalars
#pragma unroll
    for (int off = 16; off >= 1; off >>= 1) {
        tpart += __shfl_down_sync(0xffffffffu, tpart, off);
        p1    += __shfl_down_sync(0xffffffffu, p1, off);
        p2    += __shfl_down_sync(0xffffffffu, p2, off);
        p3    += __shfl_down_sync(0xffffffffu, p3, off);
    }

    if (lane == 0) {
        float d01 = wig[(long)e * 256 + 1];
        float d02 = wig[(long)e * 256 + 2];
        float d03 = wig[(long)e * 256 + 3];
        atomicAdd(&out[d * 3 + 0], p1 + d01 * tpart);
        atomicAdd(&out[d * 3 + 1], p2 + d02 * tpart);
        atomicAdd(&out[d * 3 + 2], p3 + d03 * tpart);
    }
}

// ---------------------------------------------------------------------------
extern "C" void kernel_launch(void* const* d_in, const int* in_sizes, int n_in,
                              void* d_out, int out_size)
{
    const float* x    = (const float*)d_in[0];
    const int*   zn   = (const int*)d_in[1];
    const float* dist = (const float*)d_in[2];
    const int*   eidx = (const int*)d_in[3];
    const int*   mask = (const int*)d_in[4];
    const float* wig  = (const float*)d_in[5];

    const float* fs_emb_s = (const float*)d_in[6];
    const float* fs_emb_t = (const float*)d_in[7];
    const float* fs_wd    = (const float*)d_in[8];
    const float* fs_We    = (const float*)d_in[9];
    const float* fs_Ws    = (const float*)d_in[10];
    const float* fs_Wt    = (const float*)d_in[11];
    const float* fs_Wa    = (const float*)d_in[12];
    const float* fs_va    = (const float*)d_in[13];
    const float* fs_Wv    = (const float*)d_in[14];
    const float* fs_Wo    = (const float*)d_in[15];

    const float* dn_emb_s = (const float*)d_in[16];
    const float* dn_emb_t = (const float*)d_in[17];
    const float* dn_wd    = (const float*)d_in[18];
    const float* dn_We    = (const float*)d_in[19];
    const float* dn_Ws    = (const float*)d_in[20];
    const float* dn_Wt    = (const float*)d_in[21];
    const float* dn_Wa    = (const float*)d_in[22];
    const float* dn_va    = (const float*)d_in[23];
    const float* dn_Wv    = (const float*)d_in[24];
    const float* dn_Wo    = (const float*)d_in[25];

    float* out = (float*)d_out;

    setup_kernel<<<64, 256>>>(fs_We, fs_Ws, fs_Wt, fs_Wv, fs_Wo,
                              dn_We, dn_Ws, dn_Wt, dn_Wv, dn_Wo, out);

    int blocks = (NE + 7) / 8;
    pass1_kernel<<<blocks, 256>>>(x, zn, dist, eidx, mask, wig,
                                  fs_emb_s, fs_emb_t, fs_wd, fs_We, fs_Ws, fs_Wt, fs_Wa, fs_va,
                                  dn_emb_s, dn_emb_t, dn_wd, dn_We, dn_Ws, dn_Wt, dn_Wa, dn_va);

    pass2_kernel<<<blocks, 256>>>(x, zn, dist, eidx, mask, wig,
                                  fs_emb_s, fs_emb_t, fs_wd,
                                  dn_emb_s, dn_emb_t, dn_wd, out);
}